// round 3
// baseline (speedup 1.0000x reference)
#include <cuda_runtime.h>
#include <cstdint>

// ---------------------------------------------------------------------------
// GRU, 6 layers: T=512, B=256, I=128, H=256, G=3H=768
// Output: cur [T,B,H] fp32 followed by finals [L,B,H] fp32.
// ---------------------------------------------------------------------------

#define T_LEN 512
#define B_SZ  256
#define I_SZ  128
#define H_SZ  256
#define G_SZ  768
#define L_NUM 6

#define M_ROWS (T_LEN * B_SZ)                  // 131072
#define TBH    ((size_t)T_LEN * B_SZ * H_SZ)   // 33554432
#define BH     (B_SZ * H_SZ)                   // 65536

typedef unsigned long long ull;

// ------------------------------ scratch -----------------------------------
__device__ float g_gx[(size_t)M_ROWS * G_SZ];          // 402 MB
__device__ float g_buf[2ULL * 512 * 256 * 256];        // 256 MB layer ping-pong

// ------------------------------ helpers -----------------------------------
__device__ __forceinline__ ull pack2(float x, float y) {
    ull r; asm("mov.b64 %0, {%1, %2};" : "=l"(r) : "f"(x), "f"(y)); return r;
}
__device__ __forceinline__ float2 unpack2(ull v) {
    float2 r; asm("mov.b64 {%0, %1}, %2;" : "=f"(r.x), "=f"(r.y) : "l"(v)); return r;
}
__device__ __forceinline__ void fma2(ull& d, ull a, ull b) {
    asm("fma.rn.f32x2 %0, %1, %2, %0;" : "+l"(d) : "l"(a), "l"(b));
}
__device__ __forceinline__ float tanh_f(float x) {
    float y; asm("tanh.approx.f32 %0, %1;" : "=f"(y) : "f"(x)); return y;
}
__device__ __forceinline__ float sigmf(float x) {
    return 0.5f * tanh_f(0.5f * x) + 0.5f;
}
__device__ __forceinline__ uint32_t smem_u32(const void* p) {
    uint32_t a;
    asm("{ .reg .u64 t; cvta.to.shared.u64 t, %1; cvt.u32.u64 %0, t; }"
        : "=r"(a) : "l"(p));
    return a;
}

// ------------------------------ copy --------------------------------------
__global__ void copy_kernel(float* __restrict__ dst, const float* __restrict__ src, int n) {
    int i = blockIdx.x * blockDim.x + threadIdx.x;
    if (i < n) dst[i] = src[i];
}

// ---------------------------------------------------------------------------
// Input projection GEMM: C[m][g] = bias[g] + sum_k A[m][k] * W[g][k]
// M = 131072, N = 768, K in {128, 256}. Tile 128x128x16, 256 threads,
// 8x8 per-thread microtile. Both smem tiles k-major -> inner loop is
// 4x LDS.128 per kk per thread. Staging: each thread owns one full row of
// one tile (coalesced 64B LDG, conflict-free STS).
// ---------------------------------------------------------------------------
__global__ void __launch_bounds__(256, 2)
gemm_gx_kernel(const float* __restrict__ A, const float* __restrict__ W,
               const float* __restrict__ bias, float* __restrict__ C, int K)
{
    __shared__ float As[16][132];    // [k][m], rows 16B-aligned
    __shared__ float Bs[16][132];    // [k][n]

    const int m0 = blockIdx.x * 128;
    const int n0 = blockIdx.y * 128;
    const int tid = threadIdx.x;
    const int ty = tid >> 4;         // 0..15 -> rows ty*8..+7
    const int tx = tid & 15;         // 0..15 -> cols tx*8..+7
    const int half = tid >> 7;       // 0: stage A, 1: stage B
    const int sr = tid & 127;        // staged row

    const float* src = half ? (W + (size_t)(n0 + sr) * K)
                            : (A + (size_t)(m0 + sr) * K);
    float* dst = half ? &Bs[0][sr] : &As[0][sr];

    ull acc[8][4];
    #pragma unroll
    for (int i = 0; i < 8; ++i)
        #pragma unroll
        for (int j = 0; j < 4; ++j) acc[i][j] = 0ULL;

    float rb[16];
    {
        float4 v0 = *(const float4*)(src);
        float4 v1 = *(const float4*)(src + 4);
        float4 v2 = *(const float4*)(src + 8);
        float4 v3 = *(const float4*)(src + 12);
        rb[0]=v0.x; rb[1]=v0.y; rb[2]=v0.z; rb[3]=v0.w;
        rb[4]=v1.x; rb[5]=v1.y; rb[6]=v1.z; rb[7]=v1.w;
        rb[8]=v2.x; rb[9]=v2.y; rb[10]=v2.z; rb[11]=v2.w;
        rb[12]=v3.x; rb[13]=v3.y; rb[14]=v3.z; rb[15]=v3.w;
    }

    const int nch = K >> 4;
    for (int c = 0; c < nch; ++c) {
        __syncthreads();
        #pragma unroll
        for (int j = 0; j < 16; ++j) dst[j * 132] = rb[j];
        __syncthreads();

        if (c + 1 < nch) {
            const float* sp = src + (c + 1) * 16;
            float4 v0 = *(const float4*)(sp);
            float4 v1 = *(const float4*)(sp + 4);
            float4 v2 = *(const float4*)(sp + 8);
            float4 v3 = *(const float4*)(sp + 12);
            rb[0]=v0.x; rb[1]=v0.y; rb[2]=v0.z; rb[3]=v0.w;
            rb[4]=v1.x; rb[5]=v1.y; rb[6]=v1.z; rb[7]=v1.w;
            rb[8]=v2.x; rb[9]=v2.y; rb[10]=v2.z; rb[11]=v2.w;
            rb[12]=v3.x; rb[13]=v3.y; rb[14]=v3.z; rb[15]=v3.w;
        }

        #pragma unroll
        for (int kk = 0; kk < 16; ++kk) {
            float4 a0 = *(const float4*)(&As[kk][ty * 8]);
            float4 a1 = *(const float4*)(&As[kk][ty * 8 + 4]);
            ulonglong2 bp0 = *(const ulonglong2*)(&Bs[kk][tx * 8]);
            ulonglong2 bp1 = *(const ulonglong2*)(&Bs[kk][tx * 8 + 4]);
            float av[8] = { a0.x, a0.y, a0.z, a0.w, a1.x, a1.y, a1.z, a1.w };
            #pragma unroll
            for (int i = 0; i < 8; ++i) {
                ull a2 = pack2(av[i], av[i]);
                fma2(acc[i][0], a2, bp0.x);
                fma2(acc[i][1], a2, bp0.y);
                fma2(acc[i][2], a2, bp1.x);
                fma2(acc[i][3], a2, bp1.y);
            }
        }
    }

    float4 blo = *(const float4*)(bias + n0 + tx * 8);
    float4 bhi = *(const float4*)(bias + n0 + tx * 8 + 4);
    #pragma unroll
    for (int i = 0; i < 8; ++i) {
        float2 c0 = unpack2(acc[i][0]);
        float2 c1 = unpack2(acc[i][1]);
        float2 c2 = unpack2(acc[i][2]);
        float2 c3 = unpack2(acc[i][3]);
        float4 o0 = { c0.x + blo.x, c0.y + blo.y, c1.x + blo.z, c1.y + blo.w };
        float4 o1 = { c2.x + bhi.x, c2.y + bhi.y, c3.x + bhi.z, c3.y + bhi.w };
        float* cp = C + (size_t)(m0 + ty * 8 + i) * G_SZ + n0 + tx * 8;
        *(float4*)cp = o0;
        *(float4*)(cp + 4) = o1;
    }
}

// ---------------------------------------------------------------------------
// Persistent recurrent scan for one layer, CGA-cluster version.
// Grid = 128 CTAs = 16 independent clusters of 8 (one cluster per 16-row
// b-group; the 8 CTAs split H into 8x32 columns = 96 gate columns each).
// h is double-buffered in smem and exchanged between the 8 CTAs through
// DSMEM (mapa + st.shared::cluster); barrier.cluster replaces the old
// L2-atomic grid barrier. No cross-cluster dependency exists.
// ---------------------------------------------------------------------------
#define SCAN_PAD  260
#define SCAN_SMEM (96 * 256 * 4 + 2 * 16 * SCAN_PAD * 4)   // 131584 bytes

__global__ void __launch_bounds__(128) __cluster_dims__(8, 1, 1)
gru_scan_kernel(const float* __restrict__ Whh,   // [768][256]
                const float* __restrict__ bhh,   // [768]
                const float* __restrict__ gx,    // [T*B][768]
                const float* __restrict__ hinit, // [B][256]
                float* __restrict__ out)         // [T*B][256]
{
    extern __shared__ float smem[];
    float* Ws  = smem;                       // [256][96]  k-major
    float* hsA = smem + 96 * 256;            // [16][260]
    float* hsB = hsA + 16 * SCAN_PAD;        // [16][260]

    const int tid = threadIdx.x;
    const int bg = blockIdx.x >> 3;    // 0..15 : b-group (cluster id)
    const int hg = blockIdx.x & 7;     // 0..7  : rank in cluster
    const int b0 = bg * 16;
    const int h0 = hg * 32;

    // Load + transpose W slice once: Ws[k*96 + j] = Whh[(gt*256 + h0 + col)][k]
    for (int idx = tid; idx < 96 * 256; idx += 128) {
        int j = idx >> 8;
        int k = idx & 255;
        int gt = j >> 5, col = j & 31;
        Ws[k * 96 + j] = Whh[(size_t)(gt * 256 + h0 + col) * 256 + k];
    }

    // Initial h tile: every CTA loads the full 16x256 slice for its b-group.
    for (int f = tid; f < 1024; f += 128) {
        int row = f >> 6;
        int kf = (f & 63) << 2;
        *(float4*)(hsA + row * SCAN_PAD + kf) =
            *(const float4*)(hinit + (size_t)(b0 + row) * 256 + kf);
    }

    const int w = tid >> 5;
    const int l = tid & 31;
    const int r  = l & 15;             // row 0..15 within tile
    const int cg = w * 2 + (l >> 4);   // col-group 0..7
    const int cb = h0 + cg * 4;        // global h-column base
    const int b  = b0 + r;

    float4 brv = *(const float4*)(bhh + cb);
    float4 bzv = *(const float4*)(bhh + 256 + cb);
    float4 bnv = *(const float4*)(bhh + 512 + cb);

    // smem addresses (u32) of this thread's h slot in each buffer
    const uint32_t stA = smem_u32(hsA) + (uint32_t)(r * SCAN_PAD + cb) * 4u;
    const uint32_t stB = smem_u32(hsB) + (uint32_t)(r * SCAN_PAD + cb) * 4u;

    __syncthreads();
    asm volatile("barrier.cluster.arrive.aligned;" ::: "memory");
    asm volatile("barrier.cluster.wait.aligned;"   ::: "memory");

    for (int t = 0; t < T_LEN; ++t) {
        // gx loads (independent of h): issued here, consumed after FMA loop
        const float* gxr = gx + ((size_t)t * B_SZ + b) * G_SZ;
        float4 ir  = *(const float4*)(gxr + cb);
        float4 iz  = *(const float4*)(gxr + 256 + cb);
        float4 inn = *(const float4*)(gxr + 512 + cb);

        const float* cur = (t & 1) ? hsB : hsA;
        const float* hr = cur + r * SCAN_PAD;
        const float* wp = Ws + cg * 4;

        ull aR0 = 0, aR1 = 0, aZ0 = 0, aZ1 = 0, aN0 = 0, aN1 = 0;

        #pragma unroll 4
        for (int k0 = 0; k0 < 256; k0 += 4) {
            float4 h4 = *(const float4*)(hr + k0);
            #pragma unroll
            for (int u = 0; u < 4; ++u) {
                float a = (u == 0) ? h4.x : (u == 1) ? h4.y : (u == 2) ? h4.z : h4.w;
                ull a2 = pack2(a, a);
                const float* wk = wp + (k0 + u) * 96;
                ulonglong2 wr = *(const ulonglong2*)(wk);
                ulonglong2 wz = *(const ulonglong2*)(wk + 32);
                ulonglong2 wn = *(const ulonglong2*)(wk + 64);
                fma2(aR0, a2, wr.x); fma2(aR1, a2, wr.y);
                fma2(aZ0, a2, wz.x); fma2(aZ1, a2, wz.y);
                fma2(aN0, a2, wn.x); fma2(aN1, a2, wn.y);
            }
        }

        float4 hp = *(const float4*)(hr + cb);

        float2 r01 = unpack2(aR0), r23 = unpack2(aR1);
        float2 z01 = unpack2(aZ0), z23 = unpack2(aZ1);
        float2 n01 = unpack2(aN0), n23 = unpack2(aN1);

        float rg0 = sigmf(ir.x + r01.x + brv.x);
        float rg1 = sigmf(ir.y + r01.y + brv.y);
        float rg2 = sigmf(ir.z + r23.x + brv.z);
        float rg3 = sigmf(ir.w + r23.y + brv.w);

        float zg0 = sigmf(iz.x + z01.x + bzv.x);
        float zg1 = sigmf(iz.y + z01.y + bzv.y);
        float zg2 = sigmf(iz.z + z23.x + bzv.z);
        float zg3 = sigmf(iz.w + z23.y + bzv.w);

        float ng0 = tanh_f(inn.x + rg0 * (n01.x + bnv.x));
        float ng1 = tanh_f(inn.y + rg1 * (n01.y + bnv.y));
        float ng2 = tanh_f(inn.z + rg2 * (n23.x + bnv.z));
        float ng3 = tanh_f(inn.w + rg3 * (n23.y + bnv.w));

        float4 hv;
        hv.x = (1.0f - zg0) * ng0 + zg0 * hp.x;
        hv.y = (1.0f - zg1) * ng1 + zg1 * hp.y;
        hv.z = (1.0f - zg2) * ng2 + zg2 * hp.z;
        hv.w = (1.0f - zg3) * ng3 + zg3 * hp.w;

        // broadcast own 4 h values into next-step buffer of all 8 cluster CTAs
        if (t != T_LEN - 1) {
            ull q0 = pack2(hv.x, hv.y);
            ull q1 = pack2(hv.z, hv.w);
            uint32_t lofs = (t & 1) ? stA : stB;   // next buffer
            #pragma unroll
            for (int p = 0; p < 8; ++p) {
                uint32_t ra;
                asm("mapa.shared::cluster.u32 %0, %1, %2;" : "=r"(ra) : "r"(lofs), "r"(p));
                asm volatile("st.shared::cluster.b64 [%0], %1;" :: "r"(ra), "l"(q0) : "memory");
                asm volatile("st.shared::cluster.b64 [%0], %1;" :: "r"(ra + 8), "l"(q1) : "memory");
            }
        }

        *(float4*)(out + ((size_t)t * B_SZ + b) * 256 + cb) = hv;

        if (t != T_LEN - 1) {
            asm volatile("barrier.cluster.arrive.aligned;" ::: "memory");
            asm volatile("barrier.cluster.wait.aligned;"   ::: "memory");
        }
    }
}

// ---------------------------------------------------------------------------
extern "C" void kernel_launch(void* const* d_in, const int* in_sizes, int n_in,
                              void* d_out, int out_size)
{
    const float* x     = (const float*)d_in[0];  // [512,256,128]
    const float* h0    = (const float*)d_in[1];  // [6,256,256]
    const float* Wih0  = (const float*)d_in[2];  // [768,128]
    const float* Wih   = (const float*)d_in[3];  // [5,768,256]
    const float* Whh   = (const float*)d_in[4];  // [6,768,256]
    const float* bih   = (const float*)d_in[5];  // [6,768]
    const float* bhh   = (const float*)d_in[6];  // [6,768]
    float* out = (float*)d_out;

    float *gx_p = nullptr, *buf_p = nullptr;
    cudaGetSymbolAddress((void**)&gx_p,  g_gx);
    cudaGetSymbolAddress((void**)&buf_p, g_buf);

    cudaFuncSetAttribute(gru_scan_kernel,
                         cudaFuncAttributeMaxDynamicSharedMemorySize, SCAN_SMEM);

    for (int l = 0; l < L_NUM; ++l) {
        const float* in  = (l == 0) ? x   : buf_p + (size_t)((l - 1) & 1) * TBH;
        float*       lo  = (l == L_NUM - 1) ? out : buf_p + (size_t)(l & 1) * TBH;
        const int    K   = (l == 0) ? I_SZ : H_SZ;
        const float* Wi  = (l == 0) ? Wih0 : Wih + (size_t)(l - 1) * G_SZ * H_SZ;
        const float* Wh  = Whh + (size_t)l * G_SZ * H_SZ;
        const float* bi  = bih + (size_t)l * G_SZ;
        const float* bh  = bhh + (size_t)l * G_SZ;

        // gx = in @ Wi^T + bi   for all timesteps (one big parallel GEMM)
        dim3 gg(M_ROWS / 128, G_SZ / 128);
        gemm_gx_kernel<<<gg, 256>>>(in, Wi, bi, gx_p, K);

        // recurrent scan: 16 independent clusters of 8 CTAs
        gru_scan_kernel<<<128, 128, SCAN_SMEM>>>(Wh, bh, gx_p,
                                                 h0 + (size_t)l * BH, lo);

        // finals[l] = h after 512 steps = out rows of t=511
        copy_kernel<<<BH / 256, 256>>>(out + TBH + (size_t)l * BH,
                                       lo + (size_t)511 * BH, BH);
    }
}

// round 4
// speedup vs baseline: 2.0206x; 2.0206x over previous
#include <cuda_runtime.h>
#include <cstdint>

// ---------------------------------------------------------------------------
// GRU, 6 layers: T=512, B=256, I=128, H=256, G=3H=768
// Output: cur [T,B,H] fp32 followed by finals [L,B,H] fp32.
// ---------------------------------------------------------------------------

#define T_LEN 512
#define B_SZ  256
#define I_SZ  128
#define H_SZ  256
#define G_SZ  768
#define L_NUM 6

#define M_ROWS (T_LEN * B_SZ)                  // 131072
#define TBH    ((size_t)T_LEN * B_SZ * H_SZ)   // 33554432
#define BH     (B_SZ * H_SZ)                   // 65536

typedef unsigned long long ull;

// ------------------------------ scratch -----------------------------------
__device__ float g_gx[(size_t)M_ROWS * G_SZ];          // 402 MB
__device__ float g_buf[2ULL * 512 * 256 * 256];        // 256 MB layer ping-pong
__device__ __align__(128) ull g_bar2[16][16];          // per-b-group barrier ctrs

// ------------------------------ helpers -----------------------------------
__device__ __forceinline__ ull pack2(float x, float y) {
    ull r; asm("mov.b64 %0, {%1, %2};" : "=l"(r) : "f"(x), "f"(y)); return r;
}
__device__ __forceinline__ float2 unpack2(ull v) {
    float2 r; asm("mov.b64 {%0, %1}, %2;" : "=f"(r.x), "=f"(r.y) : "l"(v)); return r;
}
__device__ __forceinline__ void fma2(ull& d, ull a, ull b) {
    asm("fma.rn.f32x2 %0, %1, %2, %0;" : "+l"(d) : "l"(a), "l"(b));
}
__device__ __forceinline__ float tanh_f(float x) {
    float y; asm("tanh.approx.f32 %0, %1;" : "=f"(y) : "f"(x)); return y;
}
__device__ __forceinline__ float sigmf(float x) {
    return 0.5f * tanh_f(0.5f * x) + 0.5f;
}

// 8-CTA barrier per b-group. release-atomic arrive + acquire poll: no
// membar.gpu, no CCTL.IVALL L1 flush. Monotonic counter -> safe across
// graph replays (all 8 members always arrive the same number of times).
__device__ __forceinline__ void bg_barrier(int bg) {
    __syncthreads();
    if (threadIdx.x == 0) {
        ull* ctr = &g_bar2[bg][0];
        ull old;
        asm volatile("atom.release.gpu.global.add.u64 %0, [%1], 1;"
                     : "=l"(old) : "l"(ctr) : "memory");
        ull target = ((old + 1ULL + 7ULL) >> 3) << 3;
        ull v;
        do {
            asm volatile("ld.acquire.gpu.global.u64 %0, [%1];"
                         : "=l"(v) : "l"(ctr) : "memory");
        } while (v < target);
    }
    __syncthreads();
}

// ------------------------------ copy --------------------------------------
__global__ void copy_kernel(float* __restrict__ dst, const float* __restrict__ src, int n) {
    int i = blockIdx.x * blockDim.x + threadIdx.x;
    if (i < n) dst[i] = src[i];
}

// ---------------------------------------------------------------------------
// Input projection GEMM: C[m][g] = bias[g] + sum_k A[m][k] * W[g][k]
// M = 131072, N = 768, K in {128, 256}. Tile 128x128x16, 256 threads,
// 8x8 per-thread microtile, k-major smem tiles, double-buffered with a
// single __syncthreads per k-chunk.
// ---------------------------------------------------------------------------
__global__ void __launch_bounds__(256, 2)
gemm_gx_kernel(const float* __restrict__ A, const float* __restrict__ W,
               const float* __restrict__ bias, float* __restrict__ C, int K)
{
    __shared__ float As[2][16][132];    // [buf][k][m]
    __shared__ float Bs[2][16][132];    // [buf][k][n]

    const int m0 = blockIdx.x * 128;
    const int n0 = blockIdx.y * 128;
    const int tid = threadIdx.x;
    const int ty = tid >> 4;         // 0..15 -> rows ty*8..+7
    const int tx = tid & 15;         // 0..15 -> cols tx*8..+7
    const int half = tid >> 7;       // 0: stage A, 1: stage B
    const int sr = tid & 127;        // staged row

    const float* src = half ? (W + (size_t)(n0 + sr) * K)
                            : (A + (size_t)(m0 + sr) * K);

    ull acc[8][4];
    #pragma unroll
    for (int i = 0; i < 8; ++i)
        #pragma unroll
        for (int j = 0; j < 4; ++j) acc[i][j] = 0ULL;

    float rb[16];
    #pragma unroll
    for (int q = 0; q < 4; ++q) {
        float4 v = *(const float4*)(src + q * 4);
        rb[q*4+0]=v.x; rb[q*4+1]=v.y; rb[q*4+2]=v.z; rb[q*4+3]=v.w;
    }
    {
        float* dst = half ? &Bs[0][0][sr] : &As[0][0][sr];
        #pragma unroll
        for (int j = 0; j < 16; ++j) dst[j * 132] = rb[j];
    }
    __syncthreads();

    const int nch = K >> 4;
    for (int c = 0; c < nch; ++c) {
        const int cur = c & 1;
        if (c + 1 < nch) {
            const float* sp = src + (c + 1) * 16;
            #pragma unroll
            for (int q = 0; q < 4; ++q) {
                float4 v = *(const float4*)(sp + q * 4);
                rb[q*4+0]=v.x; rb[q*4+1]=v.y; rb[q*4+2]=v.z; rb[q*4+3]=v.w;
            }
        }

        #pragma unroll
        for (int kk = 0; kk < 16; ++kk) {
            float4 a0 = *(const float4*)(&As[cur][kk][ty * 8]);
            float4 a1 = *(const float4*)(&As[cur][kk][ty * 8 + 4]);
            ulonglong2 bp0 = *(const ulonglong2*)(&Bs[cur][kk][tx * 8]);
            ulonglong2 bp1 = *(const ulonglong2*)(&Bs[cur][kk][tx * 8 + 4]);
            float av[8] = { a0.x, a0.y, a0.z, a0.w, a1.x, a1.y, a1.z, a1.w };
            #pragma unroll
            for (int i = 0; i < 8; ++i) {
                ull a2 = pack2(av[i], av[i]);
                fma2(acc[i][0], a2, bp0.x);
                fma2(acc[i][1], a2, bp0.y);
                fma2(acc[i][2], a2, bp1.x);
                fma2(acc[i][3], a2, bp1.y);
            }
        }

        if (c + 1 < nch) {
            float* dst = half ? &Bs[cur ^ 1][0][sr] : &As[cur ^ 1][0][sr];
            #pragma unroll
            for (int j = 0; j < 16; ++j) dst[j * 132] = rb[j];
        }
        __syncthreads();
    }

    float4 blo = *(const float4*)(bias + n0 + tx * 8);
    float4 bhi = *(const float4*)(bias + n0 + tx * 8 + 4);
    #pragma unroll
    for (int i = 0; i < 8; ++i) {
        float2 c0 = unpack2(acc[i][0]);
        float2 c1 = unpack2(acc[i][1]);
        float2 c2 = unpack2(acc[i][2]);
        float2 c3 = unpack2(acc[i][3]);
        float4 o0 = { c0.x + blo.x, c0.y + blo.y, c1.x + blo.z, c1.y + blo.w };
        float4 o1 = { c2.x + bhi.x, c2.y + bhi.y, c3.x + bhi.z, c3.y + bhi.w };
        float* cp = C + (size_t)(m0 + ty * 8 + i) * G_SZ + n0 + tx * 8;
        *(float4*)cp = o0;
        *(float4*)(cp + 4) = o1;
    }
}

// ---------------------------------------------------------------------------
// Persistent recurrent scan for one layer.
// Grid = 128 CTAs (16 b-groups x 8 h-groups), 128 threads/CTA, no clusters.
// W_hh slice (96 gate-cols x 256 k) transposed in smem for all 512 steps.
// h exchanged through `out` (global, L2-resident); reloaded with ld.cv so
// no L1 flush is ever needed. Barriers span only the 8 CTAs of one b-group.
// ---------------------------------------------------------------------------
#define SCAN_PAD  260
#define SCAN_SMEM (96 * 256 * 4 + 16 * SCAN_PAD * 4)   // 114944 bytes

__global__ void __launch_bounds__(128)
gru_scan_kernel(const float* __restrict__ Whh,   // [768][256]
                const float* __restrict__ bhh,   // [768]
                const float* __restrict__ gx,    // [T*B][768]
                const float* __restrict__ hinit, // [B][256]
                float* __restrict__ out)         // [T*B][256]
{
    extern __shared__ float smem[];
    float* Ws = smem;                    // [256][96]  k-major
    float* hs = smem + 96 * 256;         // [16][260]

    const int tid = threadIdx.x;
    const int bg = blockIdx.x >> 3;      // 0..15
    const int hg = blockIdx.x & 7;       // 0..7
    const int b0 = bg * 16;
    const int h0 = hg * 32;

    // Load + transpose W slice once: Ws[k*96 + j] = Whh[(gt*256 + h0 + col)][k]
    for (int idx = tid; idx < 96 * 256; idx += 128) {
        int j = idx >> 8;
        int k = idx & 255;
        int gt = j >> 5, col = j & 31;
        Ws[k * 96 + j] = Whh[(size_t)(gt * 256 + h0 + col) * 256 + k];
    }

    const int w = tid >> 5;
    const int l = tid & 31;
    const int r  = l & 15;             // row 0..15 within tile
    const int cg = w * 2 + (l >> 4);   // col-group 0..7
    const int cb = h0 + cg * 4;        // global h-column base
    const int b  = b0 + r;

    float4 brv = *(const float4*)(bhh + cb);
    float4 bzv = *(const float4*)(bhh + 256 + cb);
    float4 bnv = *(const float4*)(bhh + 512 + cb);

    __syncthreads();

    for (int t = 0; t < T_LEN; ++t) {
        // gx loads (independent of h) — issue before staging
        const float* gxr = gx + ((size_t)t * B_SZ + b) * G_SZ;
        float4 ir  = *(const float4*)(gxr + cb);
        float4 iz  = *(const float4*)(gxr + 256 + cb);
        float4 inn = *(const float4*)(gxr + 512 + cb);

        // stage h tile [16 x 256] -> hs. ld.cv: bypass L1 (peer CTAs wrote it).
        const float4* hsrc = (t == 0)
            ? (const float4*)(hinit + (size_t)b0 * 256)
            : (const float4*)(out + ((size_t)(t - 1) * B_SZ + b0) * 256);
        #pragma unroll
        for (int p = 0; p < 8; ++p) {
            int f = tid + p * 128;             // 0..1023
            int row = f >> 6;
            int kf = f & 63;
            float4 v = __ldcv(hsrc + row * 64 + kf);
            *(float4*)(hs + row * SCAN_PAD + kf * 4) = v;
        }
        __syncthreads();

        ull aR0 = 0, aR1 = 0, aZ0 = 0, aZ1 = 0, aN0 = 0, aN1 = 0;
        const float* hr = hs + r * SCAN_PAD;
        const float* wp = Ws + cg * 4;

        #pragma unroll 4
        for (int k0 = 0; k0 < 256; k0 += 4) {
            float4 h4 = *(const float4*)(hr + k0);
            #pragma unroll
            for (int u = 0; u < 4; ++u) {
                float a = (u == 0) ? h4.x : (u == 1) ? h4.y : (u == 2) ? h4.z : h4.w;
                ull a2 = pack2(a, a);
                const float* wk = wp + (k0 + u) * 96;
                ulonglong2 wr = *(const ulonglong2*)(wk);
                ulonglong2 wz = *(const ulonglong2*)(wk + 32);
                ulonglong2 wn = *(const ulonglong2*)(wk + 64);
                fma2(aR0, a2, wr.x); fma2(aR1, a2, wr.y);
                fma2(aZ0, a2, wz.x); fma2(aZ1, a2, wz.y);
                fma2(aN0, a2, wn.x); fma2(aN1, a2, wn.y);
            }
        }

        float4 hp = *(const float4*)(hr + cb);

        float2 r01 = unpack2(aR0), r23 = unpack2(aR1);
        float2 z01 = unpack2(aZ0), z23 = unpack2(aZ1);
        float2 n01 = unpack2(aN0), n23 = unpack2(aN1);

        float rg0 = sigmf(ir.x + r01.x + brv.x);
        float rg1 = sigmf(ir.y + r01.y + brv.y);
        float rg2 = sigmf(ir.z + r23.x + brv.z);
        float rg3 = sigmf(ir.w + r23.y + brv.w);

        float zg0 = sigmf(iz.x + z01.x + bzv.x);
        float zg1 = sigmf(iz.y + z01.y + bzv.y);
        float zg2 = sigmf(iz.z + z23.x + bzv.z);
        float zg3 = sigmf(iz.w + z23.y + bzv.w);

        float ng0 = tanh_f(inn.x + rg0 * (n01.x + bnv.x));
        float ng1 = tanh_f(inn.y + rg1 * (n01.y + bnv.y));
        float ng2 = tanh_f(inn.z + rg2 * (n23.x + bnv.z));
        float ng3 = tanh_f(inn.w + rg3 * (n23.y + bnv.w));

        float4 hv;
        hv.x = (1.0f - zg0) * ng0 + zg0 * hp.x;
        hv.y = (1.0f - zg1) * ng1 + zg1 * hp.y;
        hv.z = (1.0f - zg2) * ng2 + zg2 * hp.z;
        hv.w = (1.0f - zg3) * ng3 + zg3 * hp.w;

        *(float4*)(out + ((size_t)t * B_SZ + b) * 256 + cb) = hv;

        if (t != T_LEN - 1) bg_barrier(bg);
    }
}

// ---------------------------------------------------------------------------
extern "C" void kernel_launch(void* const* d_in, const int* in_sizes, int n_in,
                              void* d_out, int out_size)
{
    const float* x     = (const float*)d_in[0];  // [512,256,128]
    const float* h0    = (const float*)d_in[1];  // [6,256,256]
    const float* Wih0  = (const float*)d_in[2];  // [768,128]
    const float* Wih   = (const float*)d_in[3];  // [5,768,256]
    const float* Whh   = (const float*)d_in[4];  // [6,768,256]
    const float* bih   = (const float*)d_in[5];  // [6,768]
    const float* bhh   = (const float*)d_in[6];  // [6,768]
    float* out = (float*)d_out;

    float *gx_p = nullptr, *buf_p = nullptr;
    cudaGetSymbolAddress((void**)&gx_p,  g_gx);
    cudaGetSymbolAddress((void**)&buf_p, g_buf);

    cudaFuncSetAttribute(gru_scan_kernel,
                         cudaFuncAttributeMaxDynamicSharedMemorySize, SCAN_SMEM);

    for (int l = 0; l < L_NUM; ++l) {
        const float* in  = (l == 0) ? x   : buf_p + (size_t)((l - 1) & 1) * TBH;
        float*       lo  = (l == L_NUM - 1) ? out : buf_p + (size_t)(l & 1) * TBH;
        const int    K   = (l == 0) ? I_SZ : H_SZ;
        const float* Wi  = (l == 0) ? Wih0 : Wih + (size_t)(l - 1) * G_SZ * H_SZ;
        const float* Wh  = Whh + (size_t)l * G_SZ * H_SZ;
        const float* bi  = bih + (size_t)l * G_SZ;
        const float* bh  = bhh + (size_t)l * G_SZ;

        // gx = in @ Wi^T + bi   for all timesteps (one big parallel GEMM)
        dim3 gg(M_ROWS / 128, G_SZ / 128);
        gemm_gx_kernel<<<gg, 256>>>(in, Wi, bi, gx_p, K);

        // recurrent scan (128 co-resident CTAs, per-bg release/acquire barriers)
        gru_scan_kernel<<<128, 128, SCAN_SMEM>>>(Wh, bh, gx_p,
                                                 h0 + (size_t)l * BH, lo);

        // finals[l] = h after 512 steps = out rows of t=511
        copy_kernel<<<BH / 256, 256>>>(out + TBH + (size_t)l * BH,
                                       lo + (size_t)511 * BH, BH);
    }
}

// round 5
// speedup vs baseline: 2.6663x; 1.3195x over previous
#include <cuda_runtime.h>
#include <cstdint>

// ---------------------------------------------------------------------------
// GRU, 6 layers: T=512, B=256, I=128, H=256, G=3H=768
// Output: cur [T,B,H] fp32 followed by finals [L,B,H] fp32.
// ---------------------------------------------------------------------------

#define T_LEN 512
#define B_SZ  256
#define I_SZ  128
#define H_SZ  256
#define G_SZ  768
#define L_NUM 6

#define M_ROWS (T_LEN * B_SZ)                  // 131072
#define TBH    ((size_t)T_LEN * B_SZ * H_SZ)   // 33554432
#define BH     (B_SZ * H_SZ)                   // 65536

typedef unsigned long long ull;

// ------------------------------ scratch -----------------------------------
__device__ float g_gx[(size_t)M_ROWS * G_SZ];          // 402 MB
__device__ float g_buf[2ULL * 512 * 256 * 256];        // 256 MB layer ping-pong
__device__ __align__(128) ull g_bar2[16][16];          // per-b-group barrier ctrs

// ------------------------------ helpers -----------------------------------
__device__ __forceinline__ ull pack2(float x, float y) {
    ull r; asm("mov.b64 %0, {%1, %2};" : "=l"(r) : "f"(x), "f"(y)); return r;
}
__device__ __forceinline__ float2 unpack2(ull v) {
    float2 r; asm("mov.b64 {%0, %1}, %2;" : "=f"(r.x), "=f"(r.y) : "l"(v)); return r;
}
__device__ __forceinline__ void fma2(ull& d, ull a, ull b) {
    asm("fma.rn.f32x2 %0, %1, %2, %0;" : "+l"(d) : "l"(a), "l"(b));
}
__device__ __forceinline__ ull add2(ull a, ull b) {
    ull r; asm("add.rn.f32x2 %0, %1, %2;" : "=l"(r) : "l"(a), "l"(b)); return r;
}
__device__ __forceinline__ float tanh_f(float x) {
    float y; asm("tanh.approx.f32 %0, %1;" : "=f"(y) : "f"(x)); return y;
}
__device__ __forceinline__ float sigmf(float x) {
    return 0.5f * tanh_f(0.5f * x) + 0.5f;
}

// 8-CTA barrier per b-group. release-atomic arrive + acquire poll: no
// membar.gpu, no CCTL.IVALL L1 flush. Monotonic counter -> safe across
// graph replays (all 8 members always arrive the same number of times).
__device__ __forceinline__ void bg_barrier(int bg) {
    __syncthreads();
    if (threadIdx.x == 0) {
        ull* ctr = &g_bar2[bg][0];
        ull old;
        asm volatile("atom.release.gpu.global.add.u64 %0, [%1], 1;"
                     : "=l"(old) : "l"(ctr) : "memory");
        ull target = ((old + 1ULL + 7ULL) >> 3) << 3;
        if (old + 1ULL != target) {
            ull v;
            do {
                asm volatile("ld.acquire.gpu.global.u64 %0, [%1];"
                             : "=l"(v) : "l"(ctr) : "memory");
            } while (v < target);
        }
    }
    __syncthreads();
}

// ------------------------------ copy --------------------------------------
__global__ void copy_kernel(float* __restrict__ dst, const float* __restrict__ src, int n) {
    int i = blockIdx.x * blockDim.x + threadIdx.x;
    if (i < n) dst[i] = src[i];
}

// ---------------------------------------------------------------------------
// Input projection GEMM: C[m][g] = bias[g] + sum_k A[m][k] * W[g][k]
// M = 131072, N = 768, K in {128, 256}. Tile 256x128x16, 256 threads,
// 16x8 per-thread microtile (crossbar demand = 0.75 B/MAC -> fma-bound),
// k-major smem tiles, double-buffered (dynamic smem), grid n-fastest so
// concurrent CTAs share A m-blocks in L2.
// ---------------------------------------------------------------------------
#define GA_PAD 260
#define GB_PAD 132
#define GEMM_SMEM ((2 * 16 * GA_PAD + 2 * 16 * GB_PAD) * 4)   // 50176 B

__global__ void __launch_bounds__(256)
gemm_gx_kernel(const float* __restrict__ A, const float* __restrict__ W,
               const float* __restrict__ bias, float* __restrict__ C, int K)
{
    extern __shared__ float gsm[];
    float* As = gsm;                       // [2][16][260]  k-major
    float* Bs = gsm + 2 * 16 * GA_PAD;     // [2][16][132]

    const int n0 = blockIdx.x * 128;
    const int m0 = blockIdx.y * 256;
    const int tid = threadIdx.x;
    const int ty = tid >> 4;         // 0..15 -> rows ty*16..+15
    const int tx = tid & 15;         // 0..15 -> cols tx*8..+7

    const float* asrc = A + (size_t)(m0 + tid) * K;
    const float* bsrc = W + (size_t)(n0 + (tid & 127)) * K;
    const bool doB = (tid >= 128);

    ull acc[16][4];
    #pragma unroll
    for (int i = 0; i < 16; ++i)
        #pragma unroll
        for (int j = 0; j < 4; ++j) acc[i][j] = 0ULL;

    float ra[16], rb[16];
    #pragma unroll
    for (int q = 0; q < 4; ++q) {
        float4 v = *(const float4*)(asrc + q * 4);
        ra[q*4+0]=v.x; ra[q*4+1]=v.y; ra[q*4+2]=v.z; ra[q*4+3]=v.w;
    }
    if (doB) {
        #pragma unroll
        for (int q = 0; q < 4; ++q) {
            float4 v = *(const float4*)(bsrc + q * 4);
            rb[q*4+0]=v.x; rb[q*4+1]=v.y; rb[q*4+2]=v.z; rb[q*4+3]=v.w;
        }
    }
    {
        #pragma unroll
        for (int j = 0; j < 16; ++j) As[j * GA_PAD + tid] = ra[j];
        if (doB) {
            #pragma unroll
            for (int j = 0; j < 16; ++j) Bs[j * GB_PAD + (tid & 127)] = rb[j];
        }
    }
    __syncthreads();

    const int nch = K >> 4;
    for (int c = 0; c < nch; ++c) {
        const int cur = c & 1;
        const float* Ac = As + cur * 16 * GA_PAD;
        const float* Bc = Bs + cur * 16 * GB_PAD;

        if (c + 1 < nch) {
            const float* ap = asrc + (c + 1) * 16;
            #pragma unroll
            for (int q = 0; q < 4; ++q) {
                float4 v = *(const float4*)(ap + q * 4);
                ra[q*4+0]=v.x; ra[q*4+1]=v.y; ra[q*4+2]=v.z; ra[q*4+3]=v.w;
            }
            if (doB) {
                const float* bp = bsrc + (c + 1) * 16;
                #pragma unroll
                for (int q = 0; q < 4; ++q) {
                    float4 v = *(const float4*)(bp + q * 4);
                    rb[q*4+0]=v.x; rb[q*4+1]=v.y; rb[q*4+2]=v.z; rb[q*4+3]=v.w;
                }
            }
        }

        #pragma unroll
        for (int kk = 0; kk < 16; ++kk) {
            const float* ar = Ac + kk * GA_PAD + ty * 16;
            float4 a0 = *(const float4*)(ar);
            float4 a1 = *(const float4*)(ar + 4);
            float4 a2v = *(const float4*)(ar + 8);
            float4 a3 = *(const float4*)(ar + 12);
            const float* br = Bc + kk * GB_PAD + tx * 8;
            ulonglong2 bp0 = *(const ulonglong2*)(br);
            ulonglong2 bp1 = *(const ulonglong2*)(br + 4);
            float av[16] = { a0.x,a0.y,a0.z,a0.w, a1.x,a1.y,a1.z,a1.w,
                             a2v.x,a2v.y,a2v.z,a2v.w, a3.x,a3.y,a3.z,a3.w };
            #pragma unroll
            for (int i = 0; i < 16; ++i) {
                ull a2 = pack2(av[i], av[i]);
                fma2(acc[i][0], a2, bp0.x);
                fma2(acc[i][1], a2, bp0.y);
                fma2(acc[i][2], a2, bp1.x);
                fma2(acc[i][3], a2, bp1.y);
            }
        }

        if (c + 1 < nch) {
            float* Ad = As + (cur ^ 1) * 16 * GA_PAD;
            float* Bd = Bs + (cur ^ 1) * 16 * GB_PAD;
            #pragma unroll
            for (int j = 0; j < 16; ++j) Ad[j * GA_PAD + tid] = ra[j];
            if (doB) {
                #pragma unroll
                for (int j = 0; j < 16; ++j) Bd[j * GB_PAD + (tid & 127)] = rb[j];
            }
        }
        __syncthreads();
    }

    float4 blo = *(const float4*)(bias + n0 + tx * 8);
    float4 bhi = *(const float4*)(bias + n0 + tx * 8 + 4);
    #pragma unroll
    for (int i = 0; i < 16; ++i) {
        float2 c0 = unpack2(acc[i][0]);
        float2 c1 = unpack2(acc[i][1]);
        float2 c2 = unpack2(acc[i][2]);
        float2 c3 = unpack2(acc[i][3]);
        float4 o0 = { c0.x + blo.x, c0.y + blo.y, c1.x + blo.z, c1.y + blo.w };
        float4 o1 = { c2.x + bhi.x, c2.y + bhi.y, c3.x + bhi.z, c3.y + bhi.w };
        float* cp = C + (size_t)(m0 + ty * 16 + i) * G_SZ + n0 + tx * 8;
        *(float4*)cp = o0;
        *(float4*)(cp + 4) = o1;
    }
}

// ---------------------------------------------------------------------------
// Persistent recurrent scan for one layer.
// Grid = 128 CTAs (16 b-groups x 8 h-groups), 256 threads/CTA (2 warps/SMSP).
// k-split: warps 0-3 accumulate k in [0,128), warps 4-7 k in [128,256);
// partials combined through smem. W_hh slice transposed in smem for all
// 512 steps. h exchanged via `out` (ld.cv reload). Per-bg barriers.
// ---------------------------------------------------------------------------
#define SCAN_PAD  260
#define SCAN_WS   (96 * 256)
#define SCAN_HS   (16 * SCAN_PAD)
#define SCAN_SMEM ((SCAN_WS + SCAN_HS) * 4 + 128 * 6 * 8)   // 121088 B

__global__ void __launch_bounds__(256)
gru_scan_kernel(const float* __restrict__ Whh,   // [768][256]
                const float* __restrict__ bhh,   // [768]
                const float* __restrict__ gx,    // [T*B][768]
                const float* __restrict__ hinit, // [B][256]
                float* __restrict__ out)         // [T*B][256]
{
    extern __shared__ float smem[];
    float* Ws = smem;                    // [256][96]  k-major
    float* hs = smem + SCAN_WS;          // [16][260]
    ull*   red = (ull*)(smem + SCAN_WS + SCAN_HS);   // [128][6]

    const int tid = threadIdx.x;
    const int bg = blockIdx.x >> 3;      // 0..15
    const int hg = blockIdx.x & 7;       // 0..7
    const int b0 = bg * 16;
    const int h0 = hg * 32;

    // Load + transpose W slice once: Ws[k*96 + j] = Whh[(gt*256 + h0 + col)][k]
    for (int idx = tid; idx < 96 * 256; idx += 256) {
        int j = idx >> 8;
        int k = idx & 255;
        int gt = j >> 5, col = j & 31;
        Ws[k * 96 + j] = Whh[(size_t)(gt * 256 + h0 + col) * 256 + k];
    }

    const int ks = tid >> 7;           // 0/1 : k-half
    const int tl = tid & 127;
    const int w4 = tl >> 5;
    const int l  = tl & 31;
    const int r  = l & 15;             // row 0..15 within tile
    const int cg = w4 * 2 + (l >> 4);  // col-group 0..7
    const int cb = h0 + cg * 4;        // global h-column base
    const int b  = b0 + r;
    const int kbase = ks * 128;

    float4 brv = *(const float4*)(bhh + cb);
    float4 bzv = *(const float4*)(bhh + 256 + cb);
    float4 bnv = *(const float4*)(bhh + 512 + cb);

    __syncthreads();

    for (int t = 0; t < T_LEN; ++t) {
        // gx loads (independent of h) — ks=0 half only (the finalizers)
        float4 ir, iz, inn;
        if (ks == 0) {
            const float* gxr = gx + ((size_t)t * B_SZ + b) * G_SZ;
            ir  = *(const float4*)(gxr + cb);
            iz  = *(const float4*)(gxr + 256 + cb);
            inn = *(const float4*)(gxr + 512 + cb);
        }

        // stage h tile [16 x 256] -> hs. ld.cv: bypass L1 (peer CTAs wrote it).
        const float4* hsrc = (t == 0)
            ? (const float4*)(hinit + (size_t)b0 * 256)
            : (const float4*)(out + ((size_t)(t - 1) * B_SZ + b0) * 256);
        #pragma unroll
        for (int p = 0; p < 4; ++p) {
            int f = tid + p * 256;             // 0..1023
            int row = f >> 6;
            int kf = f & 63;
            float4 v = __ldcv(hsrc + row * 64 + kf);
            *(float4*)(hs + row * SCAN_PAD + kf * 4) = v;
        }
        __syncthreads();

        ull aR0 = 0, aR1 = 0, aZ0 = 0, aZ1 = 0, aN0 = 0, aN1 = 0;
        const float* hr = hs + r * SCAN_PAD;
        const float* wp = Ws + cg * 4 + kbase * 96;

        #pragma unroll 4
        for (int k0 = 0; k0 < 128; k0 += 4) {
            float4 h4 = *(const float4*)(hr + kbase + k0);
            #pragma unroll
            for (int u = 0; u < 4; ++u) {
                float a = (u == 0) ? h4.x : (u == 1) ? h4.y : (u == 2) ? h4.z : h4.w;
                ull a2 = pack2(a, a);
                const float* wk = wp + (k0 + u) * 96;
                ulonglong2 wr = *(const ulonglong2*)(wk);
                ulonglong2 wz = *(const ulonglong2*)(wk + 32);
                ulonglong2 wn = *(const ulonglong2*)(wk + 64);
                fma2(aR0, a2, wr.x); fma2(aR1, a2, wr.y);
                fma2(aZ0, a2, wz.x); fma2(aZ1, a2, wz.y);
                fma2(aN0, a2, wn.x); fma2(aN1, a2, wn.y);
            }
        }

        // combine the two k-halves
        if (ks == 1) {
            ull* rp = &red[tl * 6];
            rp[0] = aR0; rp[1] = aR1; rp[2] = aZ0;
            rp[3] = aZ1; rp[4] = aN0; rp[5] = aN1;
        }
        __syncthreads();

        if (ks == 0) {
            const ull* rp = &red[tl * 6];
            aR0 = add2(aR0, rp[0]); aR1 = add2(aR1, rp[1]);
            aZ0 = add2(aZ0, rp[2]); aZ1 = add2(aZ1, rp[3]);
            aN0 = add2(aN0, rp[4]); aN1 = add2(aN1, rp[5]);

            float4 hp = *(const float4*)(hr + cb);

            float2 r01 = unpack2(aR0), r23 = unpack2(aR1);
            float2 z01 = unpack2(aZ0), z23 = unpack2(aZ1);
            float2 n01 = unpack2(aN0), n23 = unpack2(aN1);

            float rg0 = sigmf(ir.x + r01.x + brv.x);
            float rg1 = sigmf(ir.y + r01.y + brv.y);
            float rg2 = sigmf(ir.z + r23.x + brv.z);
            float rg3 = sigmf(ir.w + r23.y + brv.w);

            float zg0 = sigmf(iz.x + z01.x + bzv.x);
            float zg1 = sigmf(iz.y + z01.y + bzv.y);
            float zg2 = sigmf(iz.z + z23.x + bzv.z);
            float zg3 = sigmf(iz.w + z23.y + bzv.w);

            float ng0 = tanh_f(inn.x + rg0 * (n01.x + bnv.x));
            float ng1 = tanh_f(inn.y + rg1 * (n01.y + bnv.y));
            float ng2 = tanh_f(inn.z + rg2 * (n23.x + bnv.z));
            float ng3 = tanh_f(inn.w + rg3 * (n23.y + bnv.w));

            float4 hv;
            hv.x = (1.0f - zg0) * ng0 + zg0 * hp.x;
            hv.y = (1.0f - zg1) * ng1 + zg1 * hp.y;
            hv.z = (1.0f - zg2) * ng2 + zg2 * hp.z;
            hv.w = (1.0f - zg3) * ng3 + zg3 * hp.w;

            *(float4*)(out + ((size_t)t * B_SZ + b) * 256 + cb) = hv;
        }

        if (t != T_LEN - 1) bg_barrier(bg);
        else __syncthreads();
    }
}

// ---------------------------------------------------------------------------
extern "C" void kernel_launch(void* const* d_in, const int* in_sizes, int n_in,
                              void* d_out, int out_size)
{
    const float* x     = (const float*)d_in[0];  // [512,256,128]
    const float* h0    = (const float*)d_in[1];  // [6,256,256]
    const float* Wih0  = (const float*)d_in[2];  // [768,128]
    const float* Wih   = (const float*)d_in[3];  // [5,768,256]
    const float* Whh   = (const float*)d_in[4];  // [6,768,256]
    const float* bih   = (const float*)d_in[5];  // [6,768]
    const float* bhh   = (const float*)d_in[6];  // [6,768]
    float* out = (float*)d_out;

    float *gx_p = nullptr, *buf_p = nullptr;
    cudaGetSymbolAddress((void**)&gx_p,  g_gx);
    cudaGetSymbolAddress((void**)&buf_p, g_buf);

    cudaFuncSetAttribute(gru_scan_kernel,
                         cudaFuncAttributeMaxDynamicSharedMemorySize, SCAN_SMEM);
    cudaFuncSetAttribute(gemm_gx_kernel,
                         cudaFuncAttributeMaxDynamicSharedMemorySize, GEMM_SMEM);

    for (int l = 0; l < L_NUM; ++l) {
        const float* in  = (l == 0) ? x   : buf_p + (size_t)((l - 1) & 1) * TBH;
        float*       lo  = (l == L_NUM - 1) ? out : buf_p + (size_t)(l & 1) * TBH;
        const int    K   = (l == 0) ? I_SZ : H_SZ;
        const float* Wi  = (l == 0) ? Wih0 : Wih + (size_t)(l - 1) * G_SZ * H_SZ;
        const float* Wh  = Whh + (size_t)l * G_SZ * H_SZ;
        const float* bi  = bih + (size_t)l * G_SZ;
        const float* bh  = bhh + (size_t)l * G_SZ;

        // gx = in @ Wi^T + bi   (n-blocks fastest so A stays L2-resident)
        dim3 gg(G_SZ / 128, M_ROWS / 256);
        gemm_gx_kernel<<<gg, 256, GEMM_SMEM>>>(in, Wi, bi, gx_p, K);

        // recurrent scan (128 co-resident CTAs, k-split, per-bg barriers)
        gru_scan_kernel<<<128, 256, SCAN_SMEM>>>(Wh, bh, gx_p,
                                                 h0 + (size_t)l * BH, lo);

        // finals[l] = h after 512 steps = out rows of t=511
        copy_kernel<<<BH / 256, 256>>>(out + TBH + (size_t)l * BH,
                                       lo + (size_t)511 * BH, BH);
    }
}

// round 6
// speedup vs baseline: 2.6664x; 1.0000x over previous
#include <cuda_runtime.h>
#include <cstdint>

// ---------------------------------------------------------------------------
// GRU, 6 layers: T=512, B=256, I=128, H=256, G=3H=768
// Output: cur [T,B,H] fp32 followed by finals [L,B,H] fp32.
// ---------------------------------------------------------------------------

#define T_LEN 512
#define B_SZ  256
#define I_SZ  128
#define H_SZ  256
#define G_SZ  768
#define L_NUM 6

#define M_ROWS (T_LEN * B_SZ)                  // 131072
#define TBH    ((size_t)T_LEN * B_SZ * H_SZ)   // 33554432
#define BH     (B_SZ * H_SZ)                   // 65536

typedef unsigned long long ull;

// ------------------------------ scratch -----------------------------------
__device__ float g_gx[(size_t)M_ROWS * G_SZ];          // 402 MB
__device__ float g_buf[2ULL * 512 * 256 * 256];        // 256 MB layer ping-pong
__device__ __align__(128) ull g_bar2[16][16];          // per-b-group barrier ctrs

// ------------------------------ helpers -----------------------------------
__device__ __forceinline__ ull pack2(float x, float y) {
    ull r; asm("mov.b64 %0, {%1, %2};" : "=l"(r) : "f"(x), "f"(y)); return r;
}
__device__ __forceinline__ float2 unpack2(ull v) {
    float2 r; asm("mov.b64 {%0, %1}, %2;" : "=f"(r.x), "=f"(r.y) : "l"(v)); return r;
}
__device__ __forceinline__ void fma2(ull& d, ull a, ull b) {
    asm("fma.rn.f32x2 %0, %1, %2, %0;" : "+l"(d) : "l"(a), "l"(b));
}
__device__ __forceinline__ ull add2(ull a, ull b) {
    ull r; asm("add.rn.f32x2 %0, %1, %2;" : "=l"(r) : "l"(a), "l"(b)); return r;
}
__device__ __forceinline__ float tanh_f(float x) {
    float y; asm("tanh.approx.f32 %0, %1;" : "=f"(y) : "f"(x)); return y;
}
__device__ __forceinline__ float sigmf(float x) {
    return 0.5f * tanh_f(0.5f * x) + 0.5f;
}

// 8-CTA barrier per b-group. release-atomic arrive + acquire poll: no
// membar.gpu, no CCTL.IVALL L1 flush. Monotonic counter -> safe across
// graph replays (all 8 members always arrive the same number of times).
__device__ __forceinline__ void bg_barrier(int bg) {
    __syncthreads();
    if (threadIdx.x == 0) {
        ull* ctr = &g_bar2[bg][0];
        ull old;
        asm volatile("atom.release.gpu.global.add.u64 %0, [%1], 1;"
                     : "=l"(old) : "l"(ctr) : "memory");
        ull target = ((old + 1ULL + 7ULL) >> 3) << 3;
        if (old + 1ULL != target) {
            ull v;
            do {
                asm volatile("ld.acquire.gpu.global.u64 %0, [%1];"
                             : "=l"(v) : "l"(ctr) : "memory");
            } while (v < target);
        }
    }
    __syncthreads();
}

// ------------------------------ copy --------------------------------------
__global__ void copy_kernel(float* __restrict__ dst, const float* __restrict__ src, int n) {
    int i = blockIdx.x * blockDim.x + threadIdx.x;
    if (i < n) dst[i] = src[i];
}

// ---------------------------------------------------------------------------
// Input projection GEMM: C[m][g] = bias[g] + sum_k A[m][k] * W[g][k]
// M = 131072, N = 768, K in {128, 256}. Tile 256x128x16, 256 threads,
// 16x8 per-thread microtile (crossbar demand = 0.75 B/MAC -> fma-bound),
// k-major smem tiles, double-buffered (dynamic smem), grid n-fastest so
// concurrent CTAs share A m-blocks in L2.
// ---------------------------------------------------------------------------
#define GA_PAD 260
#define GB_PAD 132
#define GEMM_SMEM ((2 * 16 * GA_PAD + 2 * 16 * GB_PAD) * 4)   // 50176 B

__global__ void __launch_bounds__(256)
gemm_gx_kernel(const float* __restrict__ A, const float* __restrict__ W,
               const float* __restrict__ bias, float* __restrict__ C, int K)
{
    extern __shared__ float gsm[];
    float* As = gsm;                       // [2][16][260]  k-major
    float* Bs = gsm + 2 * 16 * GA_PAD;     // [2][16][132]

    const int n0 = blockIdx.x * 128;
    const int m0 = blockIdx.y * 256;
    const int tid = threadIdx.x;
    const int ty = tid >> 4;         // 0..15 -> rows ty*16..+15
    const int tx = tid & 15;         // 0..15 -> cols tx*8..+7

    const float* asrc = A + (size_t)(m0 + tid) * K;
    const float* bsrc = W + (size_t)(n0 + (tid & 127)) * K;
    const bool doB = (tid >= 128);

    ull acc[16][4];
    #pragma unroll
    for (int i = 0; i < 16; ++i)
        #pragma unroll
        for (int j = 0; j < 4; ++j) acc[i][j] = 0ULL;

    float ra[16], rb[16];
    #pragma unroll
    for (int q = 0; q < 4; ++q) {
        float4 v = *(const float4*)(asrc + q * 4);
        ra[q*4+0]=v.x; ra[q*4+1]=v.y; ra[q*4+2]=v.z; ra[q*4+3]=v.w;
    }
    if (doB) {
        #pragma unroll
        for (int q = 0; q < 4; ++q) {
            float4 v = *(const float4*)(bsrc + q * 4);
            rb[q*4+0]=v.x; rb[q*4+1]=v.y; rb[q*4+2]=v.z; rb[q*4+3]=v.w;
        }
    }
    {
        #pragma unroll
        for (int j = 0; j < 16; ++j) As[j * GA_PAD + tid] = ra[j];
        if (doB) {
            #pragma unroll
            for (int j = 0; j < 16; ++j) Bs[j * GB_PAD + (tid & 127)] = rb[j];
        }
    }
    __syncthreads();

    const int nch = K >> 4;
    for (int c = 0; c < nch; ++c) {
        const int cur = c & 1;
        const float* Ac = As + cur * 16 * GA_PAD;
        const float* Bc = Bs + cur * 16 * GB_PAD;

        if (c + 1 < nch) {
            const float* ap = asrc + (c + 1) * 16;
            #pragma unroll
            for (int q = 0; q < 4; ++q) {
                float4 v = *(const float4*)(ap + q * 4);
                ra[q*4+0]=v.x; ra[q*4+1]=v.y; ra[q*4+2]=v.z; ra[q*4+3]=v.w;
            }
            if (doB) {
                const float* bp = bsrc + (c + 1) * 16;
                #pragma unroll
                for (int q = 0; q < 4; ++q) {
                    float4 v = *(const float4*)(bp + q * 4);
                    rb[q*4+0]=v.x; rb[q*4+1]=v.y; rb[q*4+2]=v.z; rb[q*4+3]=v.w;
                }
            }
        }

        #pragma unroll
        for (int kk = 0; kk < 16; ++kk) {
            const float* ar = Ac + kk * GA_PAD + ty * 16;
            float4 a0 = *(const float4*)(ar);
            float4 a1 = *(const float4*)(ar + 4);
            float4 a2v = *(const float4*)(ar + 8);
            float4 a3 = *(const float4*)(ar + 12);
            const float* br = Bc + kk * GB_PAD + tx * 8;
            ulonglong2 bp0 = *(const ulonglong2*)(br);
            ulonglong2 bp1 = *(const ulonglong2*)(br + 4);
            float av[16] = { a0.x,a0.y,a0.z,a0.w, a1.x,a1.y,a1.z,a1.w,
                             a2v.x,a2v.y,a2v.z,a2v.w, a3.x,a3.y,a3.z,a3.w };
            #pragma unroll
            for (int i = 0; i < 16; ++i) {
                ull a2 = pack2(av[i], av[i]);
                fma2(acc[i][0], a2, bp0.x);
                fma2(acc[i][1], a2, bp0.y);
                fma2(acc[i][2], a2, bp1.x);
                fma2(acc[i][3], a2, bp1.y);
            }
        }

        if (c + 1 < nch) {
            float* Ad = As + (cur ^ 1) * 16 * GA_PAD;
            float* Bd = Bs + (cur ^ 1) * 16 * GB_PAD;
            #pragma unroll
            for (int j = 0; j < 16; ++j) Ad[j * GA_PAD + tid] = ra[j];
            if (doB) {
                #pragma unroll
                for (int j = 0; j < 16; ++j) Bd[j * GB_PAD + (tid & 127)] = rb[j];
            }
        }
        __syncthreads();
    }

    float4 blo = *(const float4*)(bias + n0 + tx * 8);
    float4 bhi = *(const float4*)(bias + n0 + tx * 8 + 4);
    #pragma unroll
    for (int i = 0; i < 16; ++i) {
        float2 c0 = unpack2(acc[i][0]);
        float2 c1 = unpack2(acc[i][1]);
        float2 c2 = unpack2(acc[i][2]);
        float2 c3 = unpack2(acc[i][3]);
        float4 o0 = { c0.x + blo.x, c0.y + blo.y, c1.x + blo.z, c1.y + blo.w };
        float4 o1 = { c2.x + bhi.x, c2.y + bhi.y, c3.x + bhi.z, c3.y + bhi.w };
        float* cp = C + (size_t)(m0 + ty * 16 + i) * G_SZ + n0 + tx * 8;
        *(float4*)cp = o0;
        *(float4*)(cp + 4) = o1;
    }
}

// ---------------------------------------------------------------------------
// Persistent recurrent scan for one layer.
// Grid = 128 CTAs (16 b-groups x 8 h-groups), 256 threads/CTA (2 warps/SMSP).
// k-split: warps 0-3 accumulate k in [0,128), warps 4-7 k in [128,256);
// partials combined through smem. W_hh slice transposed in smem for all
// 512 steps. h exchanged via `out` (ld.cv reload). Per-bg barriers.
// ---------------------------------------------------------------------------
#define SCAN_PAD  260
#define SCAN_WS   (96 * 256)
#define SCAN_HS   (16 * SCAN_PAD)
#define SCAN_SMEM ((SCAN_WS + SCAN_HS) * 4 + 128 * 6 * 8)   // 121088 B

__global__ void __launch_bounds__(256)
gru_scan_kernel(const float* __restrict__ Whh,   // [768][256]
                const float* __restrict__ bhh,   // [768]
                const float* __restrict__ gx,    // [T*B][768]
                const float* __restrict__ hinit, // [B][256]
                float* __restrict__ out)         // [T*B][256]
{
    extern __shared__ float smem[];
    float* Ws = smem;                    // [256][96]  k-major
    float* hs = smem + SCAN_WS;          // [16][260]
    ull*   red = (ull*)(smem + SCAN_WS + SCAN_HS);   // [128][6]

    const int tid = threadIdx.x;
    const int bg = blockIdx.x >> 3;      // 0..15
    const int hg = blockIdx.x & 7;       // 0..7
    const int b0 = bg * 16;
    const int h0 = hg * 32;

    // Load + transpose W slice once: Ws[k*96 + j] = Whh[(gt*256 + h0 + col)][k]
    for (int idx = tid; idx < 96 * 256; idx += 256) {
        int j = idx >> 8;
        int k = idx & 255;
        int gt = j >> 5, col = j & 31;
        Ws[k * 96 + j] = Whh[(size_t)(gt * 256 + h0 + col) * 256 + k];
    }

    const int ks = tid >> 7;           // 0/1 : k-half
    const int tl = tid & 127;
    const int w4 = tl >> 5;
    const int l  = tl & 31;
    const int r  = l & 15;             // row 0..15 within tile
    const int cg = w4 * 2 + (l >> 4);  // col-group 0..7
    const int cb = h0 + cg * 4;        // global h-column base
    const int b  = b0 + r;
    const int kbase = ks * 128;

    float4 brv = *(const float4*)(bhh + cb);
    float4 bzv = *(const float4*)(bhh + 256 + cb);
    float4 bnv = *(const float4*)(bhh + 512 + cb);

    __syncthreads();

    for (int t = 0; t < T_LEN; ++t) {
        // gx loads (independent of h) — ks=0 half only (the finalizers)
        float4 ir, iz, inn;
        if (ks == 0) {
            const float* gxr = gx + ((size_t)t * B_SZ + b) * G_SZ;
            ir  = *(const float4*)(gxr + cb);
            iz  = *(const float4*)(gxr + 256 + cb);
            inn = *(const float4*)(gxr + 512 + cb);
        }

        // stage h tile [16 x 256] -> hs. ld.cv: bypass L1 (peer CTAs wrote it).
        const float4* hsrc = (t == 0)
            ? (const float4*)(hinit + (size_t)b0 * 256)
            : (const float4*)(out + ((size_t)(t - 1) * B_SZ + b0) * 256);
        #pragma unroll
        for (int p = 0; p < 4; ++p) {
            int f = tid + p * 256;             // 0..1023
            int row = f >> 6;
            int kf = f & 63;
            float4 v = __ldcv(hsrc + row * 64 + kf);
            *(float4*)(hs + row * SCAN_PAD + kf * 4) = v;
        }
        __syncthreads();

        ull aR0 = 0, aR1 = 0, aZ0 = 0, aZ1 = 0, aN0 = 0, aN1 = 0;
        const float* hr = hs + r * SCAN_PAD;
        const float* wp = Ws + cg * 4 + kbase * 96;

        #pragma unroll 4
        for (int k0 = 0; k0 < 128; k0 += 4) {
            float4 h4 = *(const float4*)(hr + kbase + k0);
            #pragma unroll
            for (int u = 0; u < 4; ++u) {
                float a = (u == 0) ? h4.x : (u == 1) ? h4.y : (u == 2) ? h4.z : h4.w;
                ull a2 = pack2(a, a);
                const float* wk = wp + (k0 + u) * 96;
                ulonglong2 wr = *(const ulonglong2*)(wk);
                ulonglong2 wz = *(const ulonglong2*)(wk + 32);
                ulonglong2 wn = *(const ulonglong2*)(wk + 64);
                fma2(aR0, a2, wr.x); fma2(aR1, a2, wr.y);
                fma2(aZ0, a2, wz.x); fma2(aZ1, a2, wz.y);
                fma2(aN0, a2, wn.x); fma2(aN1, a2, wn.y);
            }
        }

        // combine the two k-halves
        if (ks == 1) {
            ull* rp = &red[tl * 6];
            rp[0] = aR0; rp[1] = aR1; rp[2] = aZ0;
            rp[3] = aZ1; rp[4] = aN0; rp[5] = aN1;
        }
        __syncthreads();

        if (ks == 0) {
            const ull* rp = &red[tl * 6];
            aR0 = add2(aR0, rp[0]); aR1 = add2(aR1, rp[1]);
            aZ0 = add2(aZ0, rp[2]); aZ1 = add2(aZ1, rp[3]);
            aN0 = add2(aN0, rp[4]); aN1 = add2(aN1, rp[5]);

            float4 hp = *(const float4*)(hr + cb);

            float2 r01 = unpack2(aR0), r23 = unpack2(aR1);
            float2 z01 = unpack2(aZ0), z23 = unpack2(aZ1);
            float2 n01 = unpack2(aN0), n23 = unpack2(aN1);

            float rg0 = sigmf(ir.x + r01.x + brv.x);
            float rg1 = sigmf(ir.y + r01.y + brv.y);
            float rg2 = sigmf(ir.z + r23.x + brv.z);
            float rg3 = sigmf(ir.w + r23.y + brv.w);

            float zg0 = sigmf(iz.x + z01.x + bzv.x);
            float zg1 = sigmf(iz.y + z01.y + bzv.y);
            float zg2 = sigmf(iz.z + z23.x + bzv.z);
            float zg3 = sigmf(iz.w + z23.y + bzv.w);

            float ng0 = tanh_f(inn.x + rg0 * (n01.x + bnv.x));
            float ng1 = tanh_f(inn.y + rg1 * (n01.y + bnv.y));
            float ng2 = tanh_f(inn.z + rg2 * (n23.x + bnv.z));
            float ng3 = tanh_f(inn.w + rg3 * (n23.y + bnv.w));

            float4 hv;
            hv.x = (1.0f - zg0) * ng0 + zg0 * hp.x;
            hv.y = (1.0f - zg1) * ng1 + zg1 * hp.y;
            hv.z = (1.0f - zg2) * ng2 + zg2 * hp.z;
            hv.w = (1.0f - zg3) * ng3 + zg3 * hp.w;

            *(float4*)(out + ((size_t)t * B_SZ + b) * 256 + cb) = hv;
        }

        if (t != T_LEN - 1) bg_barrier(bg);
        else __syncthreads();
    }
}

// ---------------------------------------------------------------------------
extern "C" void kernel_launch(void* const* d_in, const int* in_sizes, int n_in,
                              void* d_out, int out_size)
{
    const float* x     = (const float*)d_in[0];  // [512,256,128]
    const float* h0    = (const float*)d_in[1];  // [6,256,256]
    const float* Wih0  = (const float*)d_in[2];  // [768,128]
    const float* Wih   = (const float*)d_in[3];  // [5,768,256]
    const float* Whh   = (const float*)d_in[4];  // [6,768,256]
    const float* bih   = (const float*)d_in[5];  // [6,768]
    const float* bhh   = (const float*)d_in[6];  // [6,768]
    float* out = (float*)d_out;

    float *gx_p = nullptr, *buf_p = nullptr;
    cudaGetSymbolAddress((void**)&gx_p,  g_gx);
    cudaGetSymbolAddress((void**)&buf_p, g_buf);

    cudaFuncSetAttribute(gru_scan_kernel,
                         cudaFuncAttributeMaxDynamicSharedMemorySize, SCAN_SMEM);
    cudaFuncSetAttribute(gemm_gx_kernel,
                         cudaFuncAttributeMaxDynamicSharedMemorySize, GEMM_SMEM);

    for (int l = 0; l < L_NUM; ++l) {
        const float* in  = (l == 0) ? x   : buf_p + (size_t)((l - 1) & 1) * TBH;
        float*       lo  = (l == L_NUM - 1) ? out : buf_p + (size_t)(l & 1) * TBH;
        const int    K   = (l == 0) ? I_SZ : H_SZ;
        const float* Wi  = (l == 0) ? Wih0 : Wih + (size_t)(l - 1) * G_SZ * H_SZ;
        const float* Wh  = Whh + (size_t)l * G_SZ * H_SZ;
        const float* bi  = bih + (size_t)l * G_SZ;
        const float* bh  = bhh + (size_t)l * G_SZ;

        // gx = in @ Wi^T + bi   (n-blocks fastest so A stays L2-resident)
        dim3 gg(G_SZ / 128, M_ROWS / 256);
        gemm_gx_kernel<<<gg, 256, GEMM_SMEM>>>(in, Wi, bi, gx_p, K);

        // recurrent scan (128 co-resident CTAs, k-split, per-bg barriers)
        gru_scan_kernel<<<128, 256, SCAN_SMEM>>>(Wh, bh, gx_p,
                                                 h0 + (size_t)l * BH, lo);

        // finals[l] = h after 512 steps = out rows of t=511
        copy_kernel<<<BH / 256, 256>>>(out + TBH + (size_t)l * BH,
                                       lo + (size_t)511 * BH, BH);
    }
}

// round 9
// speedup vs baseline: 3.0487x; 1.1434x over previous
#include <cuda_runtime.h>
#include <cuda_bf16.h>
#include <cstdint>

#define T_LEN 512
#define B_SZ  256
#define I_SZ  128
#define H_SZ  256
#define G_SZ  768
#define L_NUM 6

#define M_ROWS (T_LEN * B_SZ)                  // 131072
#define TBH    ((size_t)T_LEN * B_SZ * H_SZ)   // 33554432
#define BH     (B_SZ * H_SZ)                   // 65536

typedef unsigned long long ull;

// ------------------------------ scratch -----------------------------------
__device__ float g_gx[(size_t)M_ROWS * G_SZ];
__device__ float g_buf[2ULL * TBH];
__device__ __nv_bfloat16 g_ahi[(size_t)M_ROWS * 256];
__device__ __nv_bfloat16 g_alo[(size_t)M_ROWS * 256];
__device__ __nv_bfloat16 g_whi[G_SZ * 256];
__device__ __nv_bfloat16 g_wlo[G_SZ * 256];
__device__ __align__(128) ull g_bar2[16][16];

// ------------------------------ helpers -----------------------------------
__device__ __forceinline__ ull pack2(float x, float y) {
    ull r; asm("mov.b64 %0, {%1, %2};" : "=l"(r) : "f"(x), "f"(y)); return r;
}
__device__ __forceinline__ float2 unpack2(ull v) {
    float2 r; asm("mov.b64 {%0, %1}, %2;" : "=f"(r.x), "=f"(r.y) : "l"(v)); return r;
}
__device__ __forceinline__ void fma2(ull& d, ull a, ull b) {
    asm("fma.rn.f32x2 %0, %1, %2, %0;" : "+l"(d) : "l"(a), "l"(b));
}
__device__ __forceinline__ ull add2(ull a, ull b) {
    ull r; asm("add.rn.f32x2 %0, %1, %2;" : "=l"(r) : "l"(a), "l"(b)); return r;
}
__device__ __forceinline__ float tanh_f(float x) {
    float y; asm("tanh.approx.f32 %0, %1;" : "=f"(y) : "f"(x)); return y;
}
__device__ __forceinline__ float sigmf(float x) {
    return 0.5f * tanh_f(0.5f * x) + 0.5f;
}
__device__ __forceinline__ uint32_t smem_u32(const void* p) {
    uint32_t a;
    asm("{ .reg .u64 t; cvta.to.shared.u64 t, %1; cvt.u32.u64 %0, t; }"
        : "=r"(a) : "l"(p));
    return a;
}

// 8-CTA barrier per b-group (release arrive + acquire poll, monotonic ctr).
__device__ __forceinline__ void bg_barrier(int bg) {
    __syncthreads();
    if (threadIdx.x == 0) {
        ull* ctr = &g_bar2[bg][0];
        ull old;
        asm volatile("atom.release.gpu.global.add.u64 %0, [%1], 1;"
                     : "=l"(old) : "l"(ctr) : "memory");
        ull target = ((old + 1ULL + 7ULL) >> 3) << 3;
        if (old + 1ULL != target) {
            ull v;
            do {
                asm volatile("ld.acquire.gpu.global.u64 %0, [%1];"
                             : "=l"(v) : "l"(ctr) : "memory");
            } while (v < target);
        }
    }
    __syncthreads();
}

// ------------------------- fp32 -> bf16 hi/lo split -------------------------
__device__ __forceinline__ uint32_t bpack(float a, float b, bool lo) {
    __nv_bfloat16 ah = __float2bfloat16(a);
    __nv_bfloat16 bh = __float2bfloat16(b);
    if (lo) {
        ah = __float2bfloat16(a - __bfloat162float(ah));
        bh = __float2bfloat16(b - __bfloat162float(bh));
    }
    return (uint32_t)__bfloat16_as_ushort(ah) |
           ((uint32_t)__bfloat16_as_ushort(bh) << 16);
}

__global__ void conv_kernel(const float* __restrict__ A, const float* __restrict__ W,
                            int mk4, int wk4)
{
    int i = blockIdx.x * 256 + threadIdx.x;
    if (i < mk4) {
        float4 v = ((const float4*)A)[i];
        ((uint2*)g_ahi)[i] = make_uint2(bpack(v.x, v.y, false), bpack(v.z, v.w, false));
        ((uint2*)g_alo)[i] = make_uint2(bpack(v.x, v.y, true),  bpack(v.z, v.w, true));
    } else if (i < mk4 + wk4) {
        int j = i - mk4;
        float4 v = ((const float4*)W)[j];
        ((uint2*)g_whi)[j] = make_uint2(bpack(v.x, v.y, false), bpack(v.z, v.w, false));
        ((uint2*)g_wlo)[j] = make_uint2(bpack(v.x, v.y, true),  bpack(v.z, v.w, true));
    }
}

// ------------------------ mma.sync bf16 GEMM --------------------------------
// C[m][g] = bias[g] + sum_k A[m][k]*W[g][k] via bf16 hi/lo 3-pass.
// Tile 128x128, 8 warps (2m x 4n), K chunks of 64. Rows padded to 72 bf16.
#define GROW 72
#define GTILE (128 * GROW * 2)                 // 18432 B per tile
#define GSM_TOTAL (4 * GTILE)                  // 73728 B

__device__ __forceinline__ void ldmx4(uint32_t* r, uint32_t addr) {
    asm volatile("ldmatrix.sync.aligned.m8n8.x4.shared.b16 {%0,%1,%2,%3}, [%4];"
                 : "=r"(r[0]), "=r"(r[1]), "=r"(r[2]), "=r"(r[3]) : "r"(addr));
}
__device__ __forceinline__ void mma16816(float* d, const uint32_t* a,
                                         uint32_t b0, uint32_t b1) {
    asm volatile(
        "mma.sync.aligned.m16n8k16.row.col.f32.bf16.bf16.f32 "
        "{%0,%1,%2,%3}, {%4,%5,%6,%7}, {%8,%9}, {%0,%1,%2,%3};"
        : "+f"(d[0]), "+f"(d[1]), "+f"(d[2]), "+f"(d[3])
        : "r"(a[0]), "r"(a[1]), "r"(a[2]), "r"(a[3]), "r"(b0), "r"(b1));
}

__global__ void __launch_bounds__(256, 2)
gemm_mma_kernel(const __nv_bfloat16* __restrict__ Ahi,
                const __nv_bfloat16* __restrict__ Alo,
                const __nv_bfloat16* __restrict__ Whi,
                const __nv_bfloat16* __restrict__ Wlo,
                const float* __restrict__ bias,
                float* __restrict__ C, int K)
{
    extern __shared__ char gsm[];
    char* tAH = gsm;
    char* tAL = gsm + GTILE;
    char* tBH = gsm + 2 * GTILE;
    char* tBL = gsm + 3 * GTILE;

    const int tid = threadIdx.x;
    const int wid = tid >> 5;
    const int lane = tid & 31;
    const int wm = wid & 1;          // 0..1 : 64-row block
    const int wn = wid >> 1;         // 0..3 : 32-col block
    const int n0 = blockIdx.x * 128;
    const int m0 = blockIdx.y * 128;

    float acc[4][4][4];
    #pragma unroll
    for (int i = 0; i < 4; ++i)
        #pragma unroll
        for (int j = 0; j < 4; ++j)
            #pragma unroll
            for (int q = 0; q < 4; ++q) acc[i][j][q] = 0.0f;

    // ldmatrix lane addressing (same pattern for A and B tiles)
    const int lrow = lane & 15;
    const int lkg  = (lane >> 4) * 8;

    const int nch = K >> 6;
    for (int c = 0; c < nch; ++c) {
        // ---- stage 4 tiles (each 128 rows x 64 bf16) ----
        #pragma unroll
        for (int p = 0; p < 4; ++p) {
            int idx = p * 256 + tid;          // 0..1023
            int row = idx >> 3;
            int k8  = (idx & 7) * 8;
            size_t ga = (size_t)(m0 + row) * K + c * 64 + k8;
            size_t gb = (size_t)(n0 + row) * K + c * 64 + k8;
            uint32_t so = (uint32_t)(row * (GROW * 2) + k8 * 2);
            *(uint4*)(tAH + so) = *(const uint4*)(Ahi + ga);
            *(uint4*)(tAL + so) = *(const uint4*)(Alo + ga);
            *(uint4*)(tBH + so) = *(const uint4*)(Whi + gb);
            *(uint4*)(tBL + so) = *(const uint4*)(Wlo + gb);
        }
        __syncthreads();

        #pragma unroll
        for (int pass = 0; pass < 3; ++pass) {
            const char* At = (pass == 2) ? tAL : tAH;
            const char* Bt = (pass == 1) ? tBL : tBH;
            const uint32_t abase = smem_u32(At) +
                (uint32_t)((wm * 64 + lrow) * (GROW * 2) + lkg * 2);
            const uint32_t bbase = smem_u32(Bt) +
                (uint32_t)((wn * 32 + lrow) * (GROW * 2) + lkg * 2);

            #pragma unroll
            for (int k16 = 0; k16 < 4; ++k16) {
                uint32_t a[4][4], b[2][4];
                #pragma unroll
                for (int mt = 0; mt < 4; ++mt)
                    ldmx4(a[mt], abase + mt * 16 * (GROW * 2) + k16 * 32);
                #pragma unroll
                for (int bh = 0; bh < 2; ++bh)
                    ldmx4(b[bh], bbase + bh * 16 * (GROW * 2) + k16 * 32);
                #pragma unroll
                for (int mt = 0; mt < 4; ++mt) {
                    #pragma unroll
                    for (int nt = 0; nt < 4; ++nt) {
                        int bh = nt >> 1, sub = nt & 1;
                        mma16816(acc[mt][nt], a[mt], b[bh][sub], b[bh][sub + 2]);
                    }
                }
            }
        }
        __syncthreads();
    }

    // ---- epilogue ----
    #pragma unroll
    for (int nt = 0; nt < 4; ++nt) {
        int col = n0 + wn * 32 + nt * 8 + (lane & 3) * 2;
        float2 bv = *(const float2*)(bias + col);
        #pragma unroll
        for (int mt = 0; mt < 4; ++mt) {
            int row = m0 + wm * 64 + mt * 16 + (lane >> 2);
            float2 o0 = { acc[mt][nt][0] + bv.x, acc[mt][nt][1] + bv.y };
            float2 o1 = { acc[mt][nt][2] + bv.x, acc[mt][nt][3] + bv.y };
            *(float2*)(C + (size_t)row * G_SZ + col) = o0;
            *(float2*)(C + (size_t)(row + 8) * G_SZ + col) = o1;
        }
    }
}

// ---------------------------------------------------------------------------
// Persistent recurrent scan (proven at 15.3 ms) + finals write at t=511.
// ---------------------------------------------------------------------------
#define SCAN_PAD  260
#define SCAN_WS   (96 * 256)
#define SCAN_HS   (16 * SCAN_PAD)
#define SCAN_SMEM ((SCAN_WS + SCAN_HS) * 4 + 128 * 6 * 8)

__global__ void __launch_bounds__(256)
gru_scan_kernel(const float* __restrict__ Whh, const float* __restrict__ bhh,
                const float* __restrict__ gx, const float* __restrict__ hinit,
                float* __restrict__ out, float* __restrict__ finals)
{
    extern __shared__ float smem[];
    float* Ws = smem;
    float* hs = smem + SCAN_WS;
    ull*   red = (ull*)(smem + SCAN_WS + SCAN_HS);

    const int tid = threadIdx.x;
    const int bg = blockIdx.x >> 3;
    const int hg = blockIdx.x & 7;
    const int b0 = bg * 16;
    const int h0 = hg * 32;

    for (int idx = tid; idx < 96 * 256; idx += 256) {
        int j = idx >> 8;
        int k = idx & 255;
        int gt = j >> 5, col = j & 31;
        Ws[k * 96 + j] = Whh[(size_t)(gt * 256 + h0 + col) * 256 + k];
    }

    const int ks = tid >> 7;
    const int tl = tid & 127;
    const int w4 = tl >> 5;
    const int l  = tl & 31;
    const int r  = l & 15;
    const int cg = w4 * 2 + (l >> 4);
    const int cb = h0 + cg * 4;
    const int b  = b0 + r;
    const int kbase = ks * 128;

    float4 brv = *(const float4*)(bhh + cb);
    float4 bzv = *(const float4*)(bhh + 256 + cb);
    float4 bnv = *(const float4*)(bhh + 512 + cb);

    __syncthreads();

    for (int t = 0; t < T_LEN; ++t) {
        float4 ir, iz, inn;
        if (ks == 0) {
            const float* gxr = gx + ((size_t)t * B_SZ + b) * G_SZ;
            ir  = *(const float4*)(gxr + cb);
            iz  = *(const float4*)(gxr + 256 + cb);
            inn = *(const float4*)(gxr + 512 + cb);
        }

        const float4* hsrc = (t == 0)
            ? (const float4*)(hinit + (size_t)b0 * 256)
            : (const float4*)(out + ((size_t)(t - 1) * B_SZ + b0) * 256);
        #pragma unroll
        for (int p = 0; p < 4; ++p) {
            int f = tid + p * 256;
            int row = f >> 6;
            int kf = f & 63;
            float4 v = __ldcv(hsrc + row * 64 + kf);
            *(float4*)(hs + row * SCAN_PAD + kf * 4) = v;
        }
        __syncthreads();

        ull aR0 = 0, aR1 = 0, aZ0 = 0, aZ1 = 0, aN0 = 0, aN1 = 0;
        const float* hr = hs + r * SCAN_PAD;
        const float* wp = Ws + cg * 4 + kbase * 96;

        #pragma unroll 4
        for (int k0 = 0; k0 < 128; k0 += 4) {
            float4 h4 = *(const float4*)(hr + kbase + k0);
            #pragma unroll
            for (int u = 0; u < 4; ++u) {
                float a = (u == 0) ? h4.x : (u == 1) ? h4.y : (u == 2) ? h4.z : h4.w;
                ull a2 = pack2(a, a);
                const float* wk = wp + (k0 + u) * 96;
                ulonglong2 wr = *(const ulonglong2*)(wk);
                ulonglong2 wz = *(const ulonglong2*)(wk + 32);
                ulonglong2 wn = *(const ulonglong2*)(wk + 64);
                fma2(aR0, a2, wr.x); fma2(aR1, a2, wr.y);
                fma2(aZ0, a2, wz.x); fma2(aZ1, a2, wz.y);
                fma2(aN0, a2, wn.x); fma2(aN1, a2, wn.y);
            }
        }

        if (ks == 1) {
            ull* rp = &red[tl * 6];
            rp[0] = aR0; rp[1] = aR1; rp[2] = aZ0;
            rp[3] = aZ1; rp[4] = aN0; rp[5] = aN1;
        }
        __syncthreads();

        if (ks == 0) {
            const ull* rp = &red[tl * 6];
            aR0 = add2(aR0, rp[0]); aR1 = add2(aR1, rp[1]);
            aZ0 = add2(aZ0, rp[2]); aZ1 = add2(aZ1, rp[3]);
            aN0 = add2(aN0, rp[4]); aN1 = add2(aN1, rp[5]);

            float4 hp = *(const float4*)(hr + cb);
            float2 r01 = unpack2(aR0), r23 = unpack2(aR1);
            float2 z01 = unpack2(aZ0), z23 = unpack2(aZ1);
            float2 n01 = unpack2(aN0), n23 = unpack2(aN1);

            float rg0 = sigmf(ir.x + r01.x + brv.x);
            float rg1 = sigmf(ir.y + r01.y + brv.y);
            float rg2 = sigmf(ir.z + r23.x + brv.z);
            float rg3 = sigmf(ir.w + r23.y + brv.w);
            float zg0 = sigmf(iz.x + z01.x + bzv.x);
            float zg1 = sigmf(iz.y + z01.y + bzv.y);
            float zg2 = sigmf(iz.z + z23.x + bzv.z);
            float zg3 = sigmf(iz.w + z23.y + bzv.w);
            float ng0 = tanh_f(inn.x + rg0 * (n01.x + bnv.x));
            float ng1 = tanh_f(inn.y + rg1 * (n01.y + bnv.y));
            float ng2 = tanh_f(inn.z + rg2 * (n23.x + bnv.z));
            float ng3 = tanh_f(inn.w + rg3 * (n23.y + bnv.w));

            float4 hv;
            hv.x = (1.0f - zg0) * ng0 + zg0 * hp.x;
            hv.y = (1.0f - zg1) * ng1 + zg1 * hp.y;
            hv.z = (1.0f - zg2) * ng2 + zg2 * hp.z;
            hv.w = (1.0f - zg3) * ng3 + zg3 * hp.w;

            *(float4*)(out + ((size_t)t * B_SZ + b) * 256 + cb) = hv;
            if (t == T_LEN - 1)
                *(float4*)(finals + (size_t)b * 256 + cb) = hv;
        }

        if (t != T_LEN - 1) bg_barrier(bg);
        else __syncthreads();
    }
}

// ---------------------------------------------------------------------------
extern "C" void kernel_launch(void* const* d_in, const int* in_sizes, int n_in,
                              void* d_out, int out_size)
{
    const float* x     = (const float*)d_in[0];
    const float* h0    = (const float*)d_in[1];
    const float* Wih0  = (const float*)d_in[2];
    const float* Wih   = (const float*)d_in[3];
    const float* Whh   = (const float*)d_in[4];
    const float* bih   = (const float*)d_in[5];
    const float* bhh   = (const float*)d_in[6];
    float* out = (float*)d_out;

    float *gx_p = nullptr, *buf_p = nullptr;
    __nv_bfloat16 *ahi_p, *alo_p, *whi_p, *wlo_p;
    cudaGetSymbolAddress((void**)&gx_p,  g_gx);
    cudaGetSymbolAddress((void**)&buf_p, g_buf);
    cudaGetSymbolAddress((void**)&ahi_p, g_ahi);
    cudaGetSymbolAddress((void**)&alo_p, g_alo);
    cudaGetSymbolAddress((void**)&whi_p, g_whi);
    cudaGetSymbolAddress((void**)&wlo_p, g_wlo);

    cudaFuncSetAttribute(gru_scan_kernel,
                         cudaFuncAttributeMaxDynamicSharedMemorySize, SCAN_SMEM);
    cudaFuncSetAttribute(gemm_mma_kernel,
                         cudaFuncAttributeMaxDynamicSharedMemorySize, GSM_TOTAL);

    for (int l = 0; l < L_NUM; ++l) {
        const float* in  = (l == 0) ? x   : buf_p + (size_t)((l - 1) & 1) * TBH;
        float*       lo  = (l == L_NUM - 1) ? out : buf_p + (size_t)(l & 1) * TBH;
        const int    K   = (l == 0) ? I_SZ : H_SZ;
        const float* Wi  = (l == 0) ? Wih0 : Wih + (size_t)(l - 1) * G_SZ * H_SZ;
        const float* Wh  = Whh + (size_t)l * G_SZ * H_SZ;
        const float* bi  = bih + (size_t)l * G_SZ;
        const float* bh  = bhh + (size_t)l * G_SZ;

        int mk4 = M_ROWS * K / 4, wk4 = G_SZ * K / 4;
        conv_kernel<<<(mk4 + wk4 + 255) / 256, 256>>>(in, Wi, mk4, wk4);

        dim3 gg(G_SZ / 128, M_ROWS / 128);
        gemm_mma_kernel<<<gg, 256, GSM_TOTAL>>>(ahi_p, alo_p, whi_p, wlo_p,
                                                bi, gx_p, K);

        gru_scan_kernel<<<128, 256, SCAN_SMEM>>>(Wh, bh, gx_p,
                                                 h0 + (size_t)l * BH, lo,
                                                 out + TBH + (size_t)l * BH);
    }
}